// round 16
// baseline (speedup 1.0000x reference)
#include <cuda_runtime.h>

// SpatialGraphConv fused v4: fold-A-first, packed f32x2 FMA, persistent CTAs.
// 256 threads. GEMM: warp (tl, kci-half), 4 output channels/thread (halves
// LDS per fma2 vs v3); cross-half reduction merged into output staging.
// Fold: warp owns one (t,k) unit, thread does 2 ci rows (shares eA loads);
// conflict-free STS.128 stores.
//
// out[n,c,t,w] = sum_{kci} W[kci,c]*xa[n,t,kci,w] + sum_k b[k*128+c]*colsumA[k,w]
// xa[n,t,k*64+ci,w] = sum_v x[n,ci,t,v]*effA[k,v,w], effA = A*edge + adaptive_A

#define N_    64
#define CIN   64
#define T_    256
#define V_    25
#define K_    3
#define COUT  128
#define O_    384
#define KCI   192
#define TT    4
#define NWP   13            // live w-pairs
#define NWPP  14            // xa/eA row stride in u64 (16B aligned)
#define OS_ROW 106          // out-stage row stride in floats (53 u64, odd*? 53%16=5 -> cf)
#define THREADS 256
#define NTILES (N_ * (T_/TT))   // 4096

// ---- shared memory layout (float units) ----
#define WT_ROW 129
#define SM_WT   0
#define SM_WT_SZ (KCI*WT_ROW)                 // 24768 f
#define SM_XA   (SM_WT + SM_WT_SZ)            // u64[TT][KCI][NWPP] = 10752 u64
#define XA_U64  (TT*KCI*NWPP)
#define SM_XS   (SM_XA + 2*XA_U64)            // Xs[CIN][101]
#define XS_ROW  101
#define SM_XS_SZ (CIN*XS_ROW)                 // 6464 f
#define SM_EA   (SM_XS + SM_XS_SZ)            // effA2[K*V][NWPP]
#define EA_U64  (K_*V_*NWPP)                  // 1050 u64
#define SM_CS   (SM_EA + 2*EA_U64)            // colsum2[K][NWPP]
#define CS_U64  (K_*NWPP)                     // 42 u64
#define SM_B    (SM_CS + 2*CS_U64)            // b[384]
#define SM_TOTAL_F (SM_B + O_)                // 55304 f
#define SMEM_BYTES (SM_TOTAL_F * 4)           // 221216 B

typedef unsigned long long u64;

__device__ __forceinline__ u64 fma2(u64 a, u64 b, u64 c) {
    u64 d;
    asm("fma.rn.f32x2 %0, %1, %2, %3;" : "=l"(d) : "l"(a), "l"(b), "l"(c));
    return d;
}
__device__ __forceinline__ u64 add2(u64 a, u64 b) {
    u64 d;
    asm("add.rn.f32x2 %0, %1, %2;" : "=l"(d) : "l"(a), "l"(b));
    return d;
}
__device__ __forceinline__ u64 pack2(float x, float y) {
    u64 d;
    asm("mov.b64 %0, {%1, %2};" : "=l"(d) : "f"(x), "f"(y));
    return d;
}
__device__ __forceinline__ float2 unpack2(u64 v) {
    float2 f;
    asm("mov.b64 {%0, %1}, %2;" : "=f"(f.x), "=f"(f.y) : "l"(v));
    return f;
}

extern __shared__ float smf[];

// Fold one (utl, k) unit: thread handles ci = lane and lane+32.
__device__ __forceinline__ void fold_unit(
    int utl, int k, int lane,
    const float* __restrict__ Xs, const u64* __restrict__ eA,
    u64* __restrict__ xa)
{
    u64 a0[NWP], a1[NWP];
    #pragma unroll
    for (int p = 0; p < NWP; p++) { a0[p] = 0ull; a1[p] = 0ull; }

    const float* xr0 = Xs + lane * XS_ROW + utl * V_;
    const float* xr1 = xr0 + 32 * XS_ROW;
    const u64*   ea  = eA + k * V_ * NWPP;

    #pragma unroll 5
    for (int v = 0; v < V_; v++) {
        float x0 = xr0[v], x1 = xr1[v];
        u64 x0p = pack2(x0, x0);
        u64 x1p = pack2(x1, x1);
        const ulonglong2* e2 = (const ulonglong2*)(ea + v * NWPP);
        #pragma unroll
        for (int q = 0; q < 6; q++) {
            ulonglong2 ev = e2[q];                    // uniform LDS.128
            a0[2*q  ] = fma2(x0p, ev.x, a0[2*q  ]);
            a1[2*q  ] = fma2(x1p, ev.x, a1[2*q  ]);
            a0[2*q+1] = fma2(x0p, ev.y, a0[2*q+1]);
            a1[2*q+1] = fma2(x1p, ev.y, a1[2*q+1]);
        }
        u64 e12 = ea[v * NWPP + 12];
        a0[12] = fma2(x0p, e12, a0[12]);
        a1[12] = fma2(x1p, e12, a1[12]);
    }
    u64* xw0 = xa + ((utl * KCI) + k * 64 + lane) * NWPP;
    u64* xw1 = xw0 + 32 * NWPP;
    #pragma unroll
    for (int q = 0; q < 6; q++) {                     // STS.128, conflict-free
        ((ulonglong2*)xw0)[q] = make_ulonglong2(a0[2*q], a0[2*q+1]);
        ((ulonglong2*)xw1)[q] = make_ulonglong2(a1[2*q], a1[2*q+1]);
    }
    xw0[12] = a0[12];
    xw1[12] = a1[12];
}

__global__ void __launch_bounds__(THREADS, 1)
sgc_kernel(const float* __restrict__ x, const float* __restrict__ Wg,
           const float* __restrict__ bg, const float* __restrict__ Ag,
           const float* __restrict__ eg, const float* __restrict__ dg,
           float* __restrict__ out)
{
    float* Wt = smf + SM_WT;                 // Wt[kci][c], row 129
    u64*   xa = (u64*)(smf + SM_XA);         // xa[tl][kci][wp], row 14
    float* Xs = smf + SM_XS;                 // Xs[ci][tsl*25+v], row 101
    u64*   eA = (u64*)(smf + SM_EA);         // effA2[k*25+v][wp], row 14
    u64*   cs = (u64*)(smf + SM_CS);         // colsum2[k][wp], row 14
    float* bs = smf + SM_B;

    const int tid = threadIdx.x;

    // ---- one-time setup ----
    for (int idx = tid; idx < O_ * CIN; idx += THREADS) {
        int o  = idx >> 6;
        int ci = idx & 63;
        Wt[((o >> 7) * 64 + ci) * WT_ROW + (o & 127)] = Wg[idx];
    }
    for (int i = tid; i < O_; i += THREADS) bs[i] = bg[i];
    for (int i = tid; i < K_*V_*NWPP; i += THREADS) {
        int wp = i % NWPP;
        int kv = i / NWPP;
        float e0 = 0.f, e1 = 0.f;
        if (wp < NWP) {
            int w0 = 2 * wp;
            e0 = Ag[kv*V_ + w0] * eg[kv*V_ + w0] + dg[kv*V_ + w0];
            if (w0 + 1 < V_)
                e1 = Ag[kv*V_ + w0+1] * eg[kv*V_ + w0+1] + dg[kv*V_ + w0+1];
        }
        eA[i] = pack2(e0, e1);
    }
    __syncthreads();
    for (int i = tid; i < CS_U64; i += THREADS) {
        int k = i / NWPP, wp = i % NWPP;
        float sx = 0.f, sy = 0.f;
        for (int v = 0; v < V_; v++) {
            float2 t = unpack2(eA[(k*V_ + v)*NWPP + wp]);
            sx += t.x; sy += t.y;
        }
        cs[i] = pack2(sx, sy);
    }
    __syncthreads();

    const int wid  = tid >> 5;        // 0..7
    const int lane = tid & 31;
    const int tl   = wid & 3;         // t-slice for GEMM
    const int kh   = wid >> 2;        // 0,1: kci half

    for (int tile = blockIdx.x; tile < NTILES; tile += gridDim.x) {
        const int n  = tile >> 6;
        const int t0 = (tile & 63) * TT;

        // ---- 1) stage X: Xs[ci][tsl*25+v] = x[n][ci][t0+tsl][v] ----
        const float* xg = x + (long)n * CIN * T_ * V_ + (long)t0 * V_;
        for (int idx = tid; idx < CIN * TT * V_; idx += THREADS) {
            int ci = idx / (TT * V_);
            int r  = idx % (TT * V_);
            Xs[ci * XS_ROW + r] = xg[(long)ci * T_ * V_ + r];
        }
        __syncthreads();

        // ---- 2) fold: warps 0-3 do (utl=wid, k=0 and k=2); warps 4-7 do
        //         (utl=wid-4, k=1). Balanced per-SMSP (1950 fma2 each). ----
        if (wid < 4) {
            fold_unit(wid, 0, lane, Xs, eA, xa);
            fold_unit(wid, 2, lane, Xs, eA, xa);
        } else {
            fold_unit(wid - 4, 1, lane, Xs, eA, xa);
        }
        __syncthreads();

        // ---- 3) GEMM partial: warp (tl,kh); thread c=lane+32j (j 0..3),
        //         all 13 wp, kci in [96*kh, 96*kh+96) ----
        u64 acc[4][NWP];
        if (kh == 0) {      // bias + colsum term seeded in half 0 only
            #pragma unroll
            for (int j = 0; j < 4; j++) {
                const int c = lane + 32 * j;
                #pragma unroll
                for (int p = 0; p < NWP; p++) acc[j][p] = 0ull;
                #pragma unroll
                for (int k = 0; k < K_; k++) {
                    float bv = bs[k * COUT + c];
                    u64 bp = pack2(bv, bv);
                    #pragma unroll
                    for (int p = 0; p < NWP; p++)
                        acc[j][p] = fma2(bp, cs[k*NWPP + p], acc[j][p]);
                }
            }
        } else {
            #pragma unroll
            for (int j = 0; j < 4; j++)
                #pragma unroll
                for (int p = 0; p < NWP; p++) acc[j][p] = 0ull;
        }
        {
            const float* wr = Wt + (96 * kh) * WT_ROW + lane;
            const u64*   xr = xa + ((long)tl * KCI + 96 * kh) * NWPP;
            #pragma unroll 2
            for (int kci = 0; kci < 96; kci++) {
                float w0f = wr[0], w1f = wr[32], w2f = wr[64], w3f = wr[96];
                u64 w0 = pack2(w0f, w0f);
                u64 w1 = pack2(w1f, w1f);
                u64 w2 = pack2(w2f, w2f);
                u64 w3 = pack2(w3f, w3f);
                const ulonglong2* x2 = (const ulonglong2*)xr;
                #pragma unroll
                for (int q = 0; q < 6; q++) {
                    ulonglong2 xv = x2[q];            // uniform LDS.128
                    acc[0][2*q  ] = fma2(w0, xv.x, acc[0][2*q  ]);
                    acc[1][2*q  ] = fma2(w1, xv.x, acc[1][2*q  ]);
                    acc[2][2*q  ] = fma2(w2, xv.x, acc[2][2*q  ]);
                    acc[3][2*q  ] = fma2(w3, xv.x, acc[3][2*q  ]);
                    acc[0][2*q+1] = fma2(w0, xv.y, acc[0][2*q+1]);
                    acc[1][2*q+1] = fma2(w1, xv.y, acc[1][2*q+1]);
                    acc[2][2*q+1] = fma2(w2, xv.y, acc[2][2*q+1]);
                    acc[3][2*q+1] = fma2(w3, xv.y, acc[3][2*q+1]);
                }
                u64 xv12 = xr[12];
                acc[0][12] = fma2(w0, xv12, acc[0][12]);
                acc[1][12] = fma2(w1, xv12, acc[1][12]);
                acc[2][12] = fma2(w2, xv12, acc[2][12]);
                acc[3][12] = fma2(w3, xv12, acc[3][12]);
                wr += WT_ROW;
                xr += NWPP;
            }
        }
        __syncthreads();   // xa reads done -> region becomes out stage

        // ---- 4) reduction merged with staging: os[c][tsl*26+w], row 106 f ----
        u64* os2 = (u64*)xa;           // row = 53 u64 (bank stride 5 -> cf)
        if (kh == 1) {
            #pragma unroll
            for (int j = 0; j < 4; j++) {
                u64* row = os2 + (long)(lane + 32*j) * (OS_ROW/2) + 13 * tl;
                #pragma unroll
                for (int p = 0; p < NWP; p++) row[p] = acc[j][p];
            }
        }
        __syncthreads();
        if (kh == 0) {
            #pragma unroll
            for (int j = 0; j < 4; j++) {
                u64* row = os2 + (long)(lane + 32*j) * (OS_ROW/2) + 13 * tl;
                #pragma unroll
                for (int p = 0; p < NWP; p++) row[p] = add2(row[p], acc[j][p]);
            }
        }
        __syncthreads();

        // ---- 5) coalesced writeback: out[n][c][t0+tsl][w] ----
        const float* os = (const float*)os2;
        float* og = out + (long)n * COUT * T_ * V_ + (long)t0 * V_;
        for (int idx = tid; idx < COUT * TT * V_; idx += THREADS) {
            int c  = idx / (TT * V_);
            int rr = idx % (TT * V_);
            int tsl = rr / V_;
            int w   = rr % V_;
            og[(long)c * T_ * V_ + rr] = os[c * OS_ROW + tsl * 26 + w];
        }
        // no trailing barrier: os reads (here) are ordered before next tile's
        // fold xa-writes by the barrier after the next stage-X.
    }
}

extern "C" void kernel_launch(void* const* d_in, const int* in_sizes, int n_in,
                              void* d_out, int out_size)
{
    (void)in_sizes; (void)n_in; (void)out_size;
    const float* x    = (const float*)d_in[0];
    const float* W    = (const float*)d_in[1];
    const float* b    = (const float*)d_in[2];
    const float* A    = (const float*)d_in[3];
    const float* edge = (const float*)d_in[4];
    const float* adp  = (const float*)d_in[5];
    float* out = (float*)d_out;

    int dev = 0, nsm = 0;
    cudaGetDevice(&dev);
    cudaDeviceGetAttribute(&nsm, cudaDevAttrMultiProcessorCount, dev);
    if (nsm <= 0) nsm = 148;
    cudaFuncSetAttribute(sgc_kernel,
                         cudaFuncAttributeMaxDynamicSharedMemorySize, SMEM_BYTES);

    sgc_kernel<<<nsm, THREADS, SMEM_BYTES>>>(x, W, b, A, edge, adp, out);
}